// round 2
// baseline (speedup 1.0000x reference)
#include <cuda_runtime.h>
#include <cuda_bf16.h>
#include <float.h>

// Problem constants
#define BB 4
#define NN 1024
#define DD 1024
#define HH 16
#define DH 64
#define INNER 1024
#define BH 64          // B*H
#define MM 4096        // B*N
#define KDIM 1024
#define SCALE 0.125f

// Scratch (device globals; no allocation allowed)
__device__ float g_q[(size_t)BH * NN * DH];     // [bh, n, d]
__device__ float g_k[(size_t)BH * NN * DH];
__device__ float g_v[(size_t)BH * NN * DH];
__device__ float g_ao[(size_t)MM * INNER];      // [b, n, h, d] == [m, inner]

// ---------------------------------------------------------------------------
// Projection GEMM: C[M, Nout] = A[M,1024] @ W[1024,Nout], written to head-major
// [bh, n, d] layout. is_kv=0 -> all cols to g_q; is_kv=1 -> cols<1024 to g_k,
// cols>=1024 to g_v.
// Tiling: BM=BN=128, BK=8, 256 threads, 8x8 micro-tile (split 4+4).
// ---------------------------------------------------------------------------
__global__ __launch_bounds__(256) void proj_kernel(
    const float* __restrict__ A, const float* __restrict__ W,
    int Nout, int is_kv)
{
    __shared__ float As[8][128];
    __shared__ float Bs[8][128];
    const int bm = blockIdx.y * 128;
    const int bn = blockIdx.x * 128;
    const int tid = threadIdx.x;
    const int ty = tid >> 4, tx = tid & 15;

    float acc[8][8];
#pragma unroll
    for (int i = 0; i < 8; i++)
#pragma unroll
        for (int j = 0; j < 8; j++) acc[i][j] = 0.f;

    const int arow = tid >> 1, acol = (tid & 1) * 4;
    const int brow = tid >> 5, bcol = (tid & 31) * 4;
    const float* Aptr = A + (size_t)(bm + arow) * KDIM + acol;
    const float* Wptr = W + (size_t)brow * Nout + bn + bcol;

    for (int k0 = 0; k0 < KDIM; k0 += 8) {
        float4 a = *(const float4*)(Aptr + k0);
        float4 b = *(const float4*)(Wptr + (size_t)k0 * Nout);
        As[acol + 0][arow] = a.x;
        As[acol + 1][arow] = a.y;
        As[acol + 2][arow] = a.z;
        As[acol + 3][arow] = a.w;
        *(float4*)&Bs[brow][bcol] = b;
        __syncthreads();
#pragma unroll
        for (int kk = 0; kk < 8; kk++) {
            float ar[8], br[8];
#pragma unroll
            for (int i = 0; i < 4; i++) {
                ar[i]     = As[kk][ty * 4 + i];
                ar[4 + i] = As[kk][64 + ty * 4 + i];
            }
#pragma unroll
            for (int j = 0; j < 4; j++) {
                br[j]     = Bs[kk][tx * 4 + j];
                br[4 + j] = Bs[kk][64 + tx * 4 + j];
            }
#pragma unroll
            for (int i = 0; i < 8; i++)
#pragma unroll
                for (int j = 0; j < 8; j++) acc[i][j] += ar[i] * br[j];
        }
        __syncthreads();
    }

#pragma unroll
    for (int i = 0; i < 8; i++) {
        int m = bm + ((i < 4) ? (ty * 4 + i) : (64 + ty * 4 + i - 4));
        int bb = m >> 10, n = m & 1023;
#pragma unroll
        for (int j = 0; j < 8; j++) {
            int c = bn + ((j < 4) ? (tx * 4 + j) : (64 + tx * 4 + j - 4));
            float* dst;
            int ci = c;
            if (!is_kv) {
                dst = g_q;
            } else if (c < 1024) {
                dst = g_k;
            } else {
                dst = g_v;
                ci = c - 1024;
            }
            int h = ci >> 6, d = ci & 63;
            dst[(((size_t)(bb * 16 + h)) * 1024 + n) * 64 + d] = acc[i][j];
        }
    }
}

// ---------------------------------------------------------------------------
// Output GEMM: d_out[M,1024] = g_ao[M,1024] @ Wo[1024,1024] + bo
// ---------------------------------------------------------------------------
__global__ __launch_bounds__(256) void out_kernel(
    const float* __restrict__ W, const float* __restrict__ bias,
    float* __restrict__ out)
{
    __shared__ float As[8][128];
    __shared__ float Bs[8][128];
    const int bm = blockIdx.y * 128;
    const int bn = blockIdx.x * 128;
    const int tid = threadIdx.x;
    const int ty = tid >> 4, tx = tid & 15;

    float acc[8][8];
#pragma unroll
    for (int i = 0; i < 8; i++)
#pragma unroll
        for (int j = 0; j < 8; j++) acc[i][j] = 0.f;

    const int arow = tid >> 1, acol = (tid & 1) * 4;
    const int brow = tid >> 5, bcol = (tid & 31) * 4;
    const float* Aptr = g_ao + (size_t)(bm + arow) * KDIM + acol;
    const float* Wptr = W + (size_t)brow * 1024 + bn + bcol;

    for (int k0 = 0; k0 < KDIM; k0 += 8) {
        float4 a = *(const float4*)(Aptr + k0);
        float4 b = *(const float4*)(Wptr + (size_t)k0 * 1024);
        As[acol + 0][arow] = a.x;
        As[acol + 1][arow] = a.y;
        As[acol + 2][arow] = a.z;
        As[acol + 3][arow] = a.w;
        *(float4*)&Bs[brow][bcol] = b;
        __syncthreads();
#pragma unroll
        for (int kk = 0; kk < 8; kk++) {
            float ar[8], br[8];
#pragma unroll
            for (int i = 0; i < 4; i++) {
                ar[i]     = As[kk][ty * 4 + i];
                ar[4 + i] = As[kk][64 + ty * 4 + i];
            }
#pragma unroll
            for (int j = 0; j < 4; j++) {
                br[j]     = Bs[kk][tx * 4 + j];
                br[4 + j] = Bs[kk][64 + tx * 4 + j];
            }
#pragma unroll
            for (int i = 0; i < 8; i++)
#pragma unroll
                for (int j = 0; j < 8; j++) acc[i][j] += ar[i] * br[j];
        }
        __syncthreads();
    }

#pragma unroll
    for (int i = 0; i < 8; i++) {
        int m = bm + ((i < 4) ? (ty * 4 + i) : (64 + ty * 4 + i - 4));
#pragma unroll
        for (int j = 0; j < 8; j++) {
            int c = bn + ((j < 4) ? (tx * 4 + j) : (64 + tx * 4 + j - 4));
            out[(size_t)m * 1024 + c] = acc[i][j] + bias[c];
        }
    }
}

// ---------------------------------------------------------------------------
// Flash attention with rel_pos bias + row/col masks.
// CTA = (query tile of 64, bh). 256 threads as 16(ty: q-rows) x 16(tx).
// Key tiles of 32. Exact -FLT_MAX masking semantics (matches jnp.where + softmax).
// ---------------------------------------------------------------------------
__global__ __launch_bounds__(256) void attn_kernel(
    const float* __restrict__ rel, const int* __restrict__ qmask,
    const int* __restrict__ cmask)
{
    const int bh = blockIdx.y;          // 0..63
    const int q0 = blockIdx.x * 64;
    const int b = bh >> 4;

    __shared__ float Qs[64][65];
    __shared__ float Ks[32][65];
    __shared__ float Vs[32][65];
    __shared__ float Ss[64][33];
    __shared__ float qm[64];
    __shared__ float cm[32];

    const int tid = threadIdx.x;
    const int ty = tid >> 4, tx = tid & 15;

    // Load Q tile [64 x 64]
    const float* qbase = g_q + ((size_t)bh * NN + q0) * DH;
    for (int t = tid; t < 64 * 16; t += 256) {
        int r = t >> 4, c4 = (t & 15) * 4;
        float4 v = *(const float4*)(qbase + r * 64 + c4);
        Qs[r][c4 + 0] = v.x; Qs[r][c4 + 1] = v.y;
        Qs[r][c4 + 2] = v.z; Qs[r][c4 + 3] = v.w;
    }
    if (tid < 64) qm[tid] = (qmask[b * NN + q0 + tid] != 0) ? 1.f : 0.f;
    __syncthreads();

    float m_i[4], l_i[4], o[4][4];
#pragma unroll
    for (int i = 0; i < 4; i++) {
        m_i[i] = -FLT_MAX;
        l_i[i] = 0.f;
#pragma unroll
        for (int d = 0; d < 4; d++) o[i][d] = 0.f;
    }

    for (int j0 = 0; j0 < NN; j0 += 32) {
        const float* kbase = g_k + ((size_t)bh * NN + j0) * DH;
        const float* vbase = g_v + ((size_t)bh * NN + j0) * DH;
        for (int t = tid; t < 32 * 16; t += 256) {
            int r = t >> 4, c4 = (t & 15) * 4;
            float4 kv = *(const float4*)(kbase + r * 64 + c4);
            float4 vv = *(const float4*)(vbase + r * 64 + c4);
            Ks[r][c4 + 0] = kv.x; Ks[r][c4 + 1] = kv.y;
            Ks[r][c4 + 2] = kv.z; Ks[r][c4 + 3] = kv.w;
            Vs[r][c4 + 0] = vv.x; Vs[r][c4 + 1] = vv.y;
            Vs[r][c4 + 2] = vv.z; Vs[r][c4 + 3] = vv.w;
        }
        if (tid < 32) cm[tid] = (cmask[b * NN + j0 + tid] != 0) ? 1.f : 0.f;
        __syncthreads();

        // S = Q K^T   (each thread: 4 q-rows x 2 k-cols)
        float s[4][2];
#pragma unroll
        for (int ii = 0; ii < 4; ii++) { s[ii][0] = 0.f; s[ii][1] = 0.f; }
#pragma unroll 8
        for (int kk = 0; kk < 64; kk++) {
            float k0v = Ks[tx * 2 + 0][kk];
            float k1v = Ks[tx * 2 + 1][kk];
#pragma unroll
            for (int ii = 0; ii < 4; ii++) {
                float qv = Qs[ty * 4 + ii][kk];
                s[ii][0] += qv * k0v;
                s[ii][1] += qv * k1v;
            }
        }

        const float* relbase = rel + ((size_t)bh * NN + q0) * NN + j0;
        float c0 = cm[tx * 2 + 0];
        float c1 = cm[tx * 2 + 1];

#pragma unroll
        for (int ii = 0; ii < 4; ii++) {
            int qi = ty * 4 + ii;
            float2 r2 = *(const float2*)(relbase + (size_t)qi * NN + tx * 2);
            float s0 = s[ii][0] * SCALE + r2.x;
            float s1 = s[ii][1] * SCALE + r2.y;
            if (c0 == 0.f) s0 = -FLT_MAX;
            if (c1 == 0.f) s1 = -FLT_MAX;
            if (qm[qi] == 0.f) { s0 = -FLT_MAX; s1 = -FLT_MAX; }

            // row max across 16 tx threads
            float mx = fmaxf(s0, s1);
            mx = fmaxf(mx, __shfl_xor_sync(0xffffffffu, mx, 1));
            mx = fmaxf(mx, __shfl_xor_sync(0xffffffffu, mx, 2));
            mx = fmaxf(mx, __shfl_xor_sync(0xffffffffu, mx, 4));
            mx = fmaxf(mx, __shfl_xor_sync(0xffffffffu, mx, 8));

            float m_new = fmaxf(m_i[ii], mx);
            float alpha = __expf(m_i[ii] - m_new);   // exp(0)=1 when both -FLT_MAX
            float p0 = __expf(s0 - m_new);
            float p1 = __expf(s1 - m_new);
            float rs = p0 + p1;
            rs += __shfl_xor_sync(0xffffffffu, rs, 1);
            rs += __shfl_xor_sync(0xffffffffu, rs, 2);
            rs += __shfl_xor_sync(0xffffffffu, rs, 4);
            rs += __shfl_xor_sync(0xffffffffu, rs, 8);

            l_i[ii] = l_i[ii] * alpha + rs;
            m_i[ii] = m_new;
#pragma unroll
            for (int d = 0; d < 4; d++) o[ii][d] *= alpha;
            Ss[qi][tx * 2 + 0] = p0;
            Ss[qi][tx * 2 + 1] = p1;
        }
        __syncthreads();

        // O += P V   (each thread: 4 q-rows x 4 dims at cols tx*4..tx*4+3)
#pragma unroll 4
        for (int j = 0; j < 32; j++) {
            float vv[4];
#pragma unroll
            for (int d = 0; d < 4; d++) vv[d] = Vs[j][tx * 4 + d];
#pragma unroll
            for (int ii = 0; ii < 4; ii++) {
                float pij = Ss[ty * 4 + ii][j];
#pragma unroll
                for (int d = 0; d < 4; d++) o[ii][d] += pij * vv[d];
            }
        }
        __syncthreads();
    }

    // finalize: divide by l, write to [b, n, h, d]
    const int h = bh & 15;
#pragma unroll
    for (int ii = 0; ii < 4; ii++) {
        int qi = q0 + ty * 4 + ii;
        float inv = 1.f / l_i[ii];
        float* dst = g_ao + (((size_t)b * NN + qi) * HH + h) * DH + tx * 4;
        float4 w;
        w.x = o[ii][0] * inv; w.y = o[ii][1] * inv;
        w.z = o[ii][2] * inv; w.w = o[ii][3] * inv;
        *(float4*)dst = w;
    }
}

// ---------------------------------------------------------------------------
// Launch
// Inputs (metadata order): x, rel_pos, query_mask, context_mask, Wq, Wkv, Wo, bo
// ---------------------------------------------------------------------------
extern "C" void kernel_launch(void* const* d_in, const int* in_sizes, int n_in,
                              void* d_out, int out_size) {
    const float* x    = (const float*)d_in[0];
    const float* rel  = (const float*)d_in[1];
    const int*   qmsk = (const int*)d_in[2];
    const int*   cmsk = (const int*)d_in[3];
    const float* Wq   = (const float*)d_in[4];
    const float* Wkv  = (const float*)d_in[5];
    const float* Wo   = (const float*)d_in[6];
    const float* bo   = (const float*)d_in[7];
    float* out = (float*)d_out;

    // Q projection: M=4096 x Nout=1024
    proj_kernel<<<dim3(1024 / 128, 4096 / 128), 256>>>(x, Wq, 1024, 0);
    // KV projection: M=4096 x Nout=2048
    proj_kernel<<<dim3(2048 / 128, 4096 / 128), 256>>>(x, Wkv, 2048, 1);
    // Attention: 16 query tiles x 64 (b,h)
    attn_kernel<<<dim3(NN / 64, BH), 256>>>(rel, qmsk, cmsk);
    // Output projection + bias
    out_kernel<<<dim3(1024 / 128, 4096 / 128), 256>>>(Wo, bo, out);
}